// round 3
// baseline (speedup 1.0000x reference)
#include <cuda_runtime.h>

#define BB 8
#define NN 1024
#define HIDD 256
#define HEADS 8
#define DHH 32
#define EPER 16384
#define KKP 512

// ---- output layout (float32, concatenated flattened outputs) ----
#define OFF_ENC   0
#define OFF_SUBX  (BB*NN*HIDD)                       // 2097152
#define OFF_EDGE  (OFF_SUBX + BB*KKP*HIDD)           // 3145728
#define OFF_PERM  (OFF_EDGE + BB*2*EPER)             // 3407872
#define OFF_VALID (OFF_PERM + BB*KKP)                // 3411968

// ---- device scratch (no allocations allowed; referenced directly in device code) ----
__device__ float g_Q[BB*NN*HIDD];
__device__ float g_K[BB*NN*HIDD];
__device__ float g_V[BB*NN*HIDD];
__device__ float g_AO[BB*NN*HIDD];
__device__ float g_ENC[BB*NN*HIDD];
__device__ float g_score[BB*NN];
__device__ int   g_perm[BB*KKP];
__device__ float g_vals[BB*KKP];
__device__ int   g_nodemap[BB*NN];
__device__ unsigned long long g_es[BB*EPER];

// ============================================================
// GEMM: C[8192,256] = A[8192,256] @ W[256,256]
// sel 0/1/2: A=Aparam, C=g_Q/g_K/g_V.  sel 3: A=g_AO, C=g_ENC + out2.
// 64x64 tile, 256 threads, 4x4 microtile, K-chunks of 16. Static smem 8KB.
// ============================================================
__global__ __launch_bounds__(256) void gemm_k(
    const float* __restrict__ Aparam, const float* __restrict__ W,
    int sel, float* __restrict__ out2)
{
    const float* A;
    float* C;
    if      (sel == 0) { A = Aparam; C = g_Q; }
    else if (sel == 1) { A = Aparam; C = g_K; }
    else if (sel == 2) { A = Aparam; C = g_V; }
    else               { A = g_AO;   C = g_ENC; }

    __shared__ float As[16][64];
    __shared__ float Ws[16][64];
    const int tx = threadIdx.x & 15;
    const int ty = threadIdx.x >> 4;
    const int rowBase = blockIdx.y * 64;
    const int colBase = blockIdx.x * 64;
    float acc[4][4];
    #pragma unroll
    for (int i = 0; i < 4; i++)
        #pragma unroll
        for (int j = 0; j < 4; j++) acc[i][j] = 0.f;

    const int t  = threadIdx.x;
    const int ar = t >> 2,  ac = (t & 3) << 2;
    const int wr = t >> 4,  wc = (t & 15) << 2;

    for (int k0 = 0; k0 < 256; k0 += 16) {
        float4 a4 = *(const float4*)(A + (rowBase + ar) * 256 + k0 + ac);
        As[ac + 0][ar] = a4.x; As[ac + 1][ar] = a4.y;
        As[ac + 2][ar] = a4.z; As[ac + 3][ar] = a4.w;
        *(float4*)(&Ws[wr][wc]) = *(const float4*)(W + (k0 + wr) * 256 + colBase + wc);
        __syncthreads();
        #pragma unroll
        for (int kk = 0; kk < 16; kk++) {
            float4 a = *(const float4*)(&As[kk][ty << 2]);
            float4 w = *(const float4*)(&Ws[kk][tx << 2]);
            acc[0][0] += a.x * w.x; acc[0][1] += a.x * w.y; acc[0][2] += a.x * w.z; acc[0][3] += a.x * w.w;
            acc[1][0] += a.y * w.x; acc[1][1] += a.y * w.y; acc[1][2] += a.y * w.z; acc[1][3] += a.y * w.w;
            acc[2][0] += a.z * w.x; acc[2][1] += a.z * w.y; acc[2][2] += a.z * w.z; acc[2][3] += a.z * w.w;
            acc[3][0] += a.w * w.x; acc[3][1] += a.w * w.y; acc[3][2] += a.w * w.z; acc[3][3] += a.w * w.w;
        }
        __syncthreads();
    }
    #pragma unroll
    for (int i = 0; i < 4; i++) {
        int row = rowBase + (ty << 2) + i;
        float4 v = make_float4(acc[i][0], acc[i][1], acc[i][2], acc[i][3]);
        *(float4*)(C + row * 256 + colBase + (tx << 2)) = v;
        if (sel == 3) *(float4*)(out2 + row * 256 + colBase + (tx << 2)) = v;
    }
}

// ============================================================
// Attention: block = (32-q tile, b), 256 threads = 8 heads x 32 q.
// Thread owns one (h,q) row: online softmax, K/V (k-tile 16) in static smem.
// ============================================================
__global__ __launch_bounds__(256) void attn_kernel(const float* __restrict__ dist)
{
    __shared__ float Ks[16 * 256];
    __shared__ float Vs[16 * 256];
    __shared__ float ds[32 * 17];

    const int b = blockIdx.y;
    const int qbase = blockIdx.x * 32;
    const int t = threadIdx.x;
    const int h = t >> 5, q = t & 31;

    const float* qp = g_Q + ((long)(b * NN + qbase + q)) * HIDD + (h << 5);
    float qv[32];
    #pragma unroll
    for (int d4 = 0; d4 < 8; d4++) {
        float4 v = ((const float4*)qp)[d4];
        qv[4*d4+0] = v.x; qv[4*d4+1] = v.y; qv[4*d4+2] = v.z; qv[4*d4+3] = v.w;
    }

    float m = -1e30f, l = 0.f, o[32];
    #pragma unroll
    for (int d = 0; d < 32; d++) o[d] = 0.f;
    const float scale = 0.1767766952966369f;  // 1/sqrt(32)

    for (int kt = 0; kt < 64; kt++) {
        const int kbase = kt * 16;
        const float* Kg = g_K + ((long)(b * NN + kbase)) * HIDD;
        const float* Vg = g_V + ((long)(b * NN + kbase)) * HIDD;
        __syncthreads();
        for (int idx = t; idx < 1024; idx += 256) {   // 16*256 floats = 1024 float4
            ((float4*)Ks)[idx] = ((const float4*)Kg)[idx];
            ((float4*)Vs)[idx] = ((const float4*)Vg)[idx];
        }
        for (int idx = t; idx < 512; idx += 256) {    // 32 q x 16 k
            int qq = idx >> 4, kk = idx & 15;
            ds[qq * 17 + kk] = dist[((long)(b * NN + qbase + qq)) * NN + kbase + kk];
        }
        __syncthreads();

        float sv[16];
        float smax = -1e30f;
        #pragma unroll
        for (int kk = 0; kk < 16; kk++) {
            const float4* kp = (const float4*)(Ks + kk * 256 + (h << 5));
            float s = 0.f;
            #pragma unroll
            for (int d4 = 0; d4 < 8; d4++) {
                float4 k4 = kp[d4];
                s += qv[d4*4+0]*k4.x + qv[d4*4+1]*k4.y + qv[d4*4+2]*k4.z + qv[d4*4+3]*k4.w;
            }
            s = s * scale + ds[q * 17 + kk];
            sv[kk] = s;
            smax = fmaxf(smax, s);
        }
        float mnew = fmaxf(m, smax);
        float corr = __expf(m - mnew);
        l *= corr;
        #pragma unroll
        for (int d = 0; d < 32; d++) o[d] *= corr;
        #pragma unroll
        for (int kk = 0; kk < 16; kk++) {
            float p = __expf(sv[kk] - mnew);
            l += p;
            const float4* vp = (const float4*)(Vs + kk * 256 + (h << 5));
            #pragma unroll
            for (int d4 = 0; d4 < 8; d4++) {
                float4 v4 = vp[d4];
                o[d4*4+0] += p * v4.x; o[d4*4+1] += p * v4.y;
                o[d4*4+2] += p * v4.z; o[d4*4+3] += p * v4.w;
            }
        }
        m = mnew;
    }

    float inv = 1.f / l;
    float* op = g_AO + ((long)(b * NN + qbase + q)) * HIDD + (h << 5);
    #pragma unroll
    for (int d4 = 0; d4 < 8; d4++) {
        float4 v = make_float4(o[4*d4+0]*inv, o[4*d4+1]*inv, o[4*d4+2]*inv, o[4*d4+3]*inv);
        ((float4*)op)[d4] = v;
    }
}

// ============================================================
// Node scores: s = tanh((x . w) / ||w||). One warp per node.
// ============================================================
__global__ __launch_bounds__(256) void score_kernel(const float* __restrict__ w)
{
    int warp = (blockIdx.x * blockDim.x + threadIdx.x) >> 5;
    int lane = threadIdx.x & 31;
    if (warp >= BB * NN) return;
    const float* x = g_ENC + (long)warp * HIDD;
    float sx = 0.f, sw = 0.f;
    #pragma unroll
    for (int i = lane; i < HIDD; i += 32) {
        float wv = w[i];
        sx += x[i] * wv;
        sw += wv * wv;
    }
    #pragma unroll
    for (int off = 16; off; off >>= 1) {
        sx += __shfl_xor_sync(0xFFFFFFFFu, sx, off);
        sw += __shfl_xor_sync(0xFFFFFFFFu, sw, off);
    }
    if (lane == 0) g_score[warp] = tanhf(sx / sqrtf(sw));
}

// ============================================================
// Top-K per graph: bitonic sort of 1024 (desc score, asc index). 8KB smem.
// ============================================================
__global__ __launch_bounds__(1024) void topk_kernel(float* __restrict__ out_perm)
{
    __shared__ unsigned long long s[NN];
    const int b = blockIdx.x, t = threadIdx.x;
    float sc = g_score[b * NN + t];
    unsigned u = __float_as_uint(sc);
    u = (u & 0x80000000u) ? ~u : (u | 0x80000000u);   // monotonic map
    u = ~u;                                            // descending
    s[t] = (((unsigned long long)u) << 32) | (unsigned)t;
    g_nodemap[b * NN + t] = -1;
    __syncthreads();
    for (unsigned k = 2; k <= NN; k <<= 1)
        for (unsigned j = k >> 1; j; j >>= 1) {
            unsigned i = t, ixj = i ^ j;
            if (ixj > i) {
                bool up = ((i & k) == 0);
                unsigned long long a = s[i], c = s[ixj];
                if ((a > c) == up) { s[i] = c; s[ixj] = a; }
            }
            __syncthreads();
        }
    if (t < KKP) {
        int node = (int)(s[t] & 0xFFFFFFFFu);
        g_perm[b * KKP + t] = node;
        g_vals[b * KKP + t] = g_score[b * NN + node];
        out_perm[b * KKP + t] = (float)node;
        g_nodemap[b * NN + node] = t;
    }
}

// ============================================================
// sub_x gather: sub_x[b,j,:] = enc[b, perm[j], :] * vals[j]
// ============================================================
__global__ __launch_bounds__(256) void subx_kernel(float* __restrict__ out)
{
    const int row = blockIdx.x;           // 0..B*K-1
    const int b = row / KKP;
    const int node = g_perm[row];
    const float val = g_vals[row];
    const float* src = g_ENC + ((long)b * NN + node) * HIDD;
    out[(long)row * HIDD + threadIdx.x] = src[threadIdx.x] * val;
}

// ============================================================
// Edge remap + hybrid bitonic sort (16384/graph) + emit.
// edge_index dtype detected at runtime (int64 vs int32 delivery);
// indices clamped so no interpretation can generate a wild address.
// Packed: key(19b) << 21 | (ou+1)<<11 | (ov+1)<<1 | valid.
// Equal keys => equal payloads, so key-sort matches stable argsort.
// ============================================================
__global__ __launch_bounds__(1024) void edge_kernel(
    const void* __restrict__ eiraw,
    float* __restrict__ out_e, float* __restrict__ out_valid)
{
    __shared__ unsigned long long sh[4096];
    __shared__ int s_is64;
    const int b = blockIdx.x, t = threadIdx.x;
    unsigned long long* es = g_es + (long)b * EPER;

    if (t == 0) {
        // if int64: node ids < 8192 => every odd 32-bit word is 0
        const unsigned* w32 = (const unsigned*)eiraw;
        int all0 = 1;
        for (int i = 0; i < 64; i++)
            if (w32[2 * i + 1] != 0u) { all0 = 0; break; }
        s_is64 = all0;
    }
    __syncthreads();
    const int is64 = s_is64;

    for (int e = t; e < EPER; e += 1024) {
        long long vs, vd;
        if (is64) {
            const long long* ei = (const long long*)eiraw;
            vs = ei[(long)b * EPER + e];
            vd = ei[(long)BB * EPER + (long)b * EPER + e];
        } else {
            const int* ei = (const int*)eiraw;
            vs = ei[b * EPER + e];
            vd = ei[BB * EPER + b * EPER + e];
        }
        int src = (int)(vs - (long long)b * NN);
        int dst = (int)(vd - (long long)b * NN);
        src = min(max(src, 0), NN - 1);   // safety clamp (no-op for sane input)
        dst = min(max(dst, 0), NN - 1);
        int nu = g_nodemap[b * NN + src];
        int nv = g_nodemap[b * NN + dst];
        bool valid = (nu >= 0) && (nv >= 0);
        unsigned key = valid ? (unsigned)(nu * KKP + nv) : (unsigned)(KKP * KKP);
        int ou = valid ? nu : -1, ov = valid ? nv : -1;
        es[e] = (((unsigned long long)key) << 21)
              | (((unsigned long long)(ou + 1)) << 11)
              | (((unsigned long long)(ov + 1)) << 1)
              | (valid ? 1ull : 0ull);
    }
    __syncthreads();

    // Phase 1: fully sort each 4096-segment in shared.
    for (int seg = 0; seg < 4; seg++) {
        for (int i = t; i < 4096; i += 1024) sh[i] = es[seg * 4096 + i];
        __syncthreads();
        for (unsigned k = 2; k <= 4096; k <<= 1)
            for (unsigned j = k >> 1; j; j >>= 1) {
                for (int loc = t; loc < 4096; loc += 1024) {
                    unsigned i2 = (unsigned)loc, ixj = i2 ^ j;
                    if (ixj > i2) {
                        unsigned gi = seg * 4096 + i2;
                        bool up = ((gi & k) == 0);
                        unsigned long long a = sh[i2], c = sh[ixj];
                        if ((a > c) == up) { sh[i2] = c; sh[ixj] = a; }
                    }
                }
                __syncthreads();
            }
        for (int i = t; i < 4096; i += 1024) es[seg * 4096 + i] = sh[i];
        __syncthreads();
    }

    // Phase 2: k = 8192, 16384. Global for j >= 4096, shared for j <= 2048.
    for (unsigned k = 8192; k <= 16384; k <<= 1) {
        for (unsigned j = k >> 1; j >= 4096; j >>= 1) {
            for (int loc = t; loc < EPER; loc += 1024) {
                unsigned i2 = (unsigned)loc, ixj = i2 ^ j;
                if (ixj > i2) {
                    bool up = ((i2 & k) == 0);
                    unsigned long long a = es[i2], c = es[ixj];
                    if ((a > c) == up) { es[i2] = c; es[ixj] = a; }
                }
            }
            __syncthreads();
        }
        for (int seg = 0; seg < 4; seg++) {
            for (int i = t; i < 4096; i += 1024) sh[i] = es[seg * 4096 + i];
            __syncthreads();
            for (unsigned j = 2048; j; j >>= 1) {
                for (int loc = t; loc < 4096; loc += 1024) {
                    unsigned i2 = (unsigned)loc, ixj = i2 ^ j;
                    if (ixj > i2) {
                        unsigned gi = seg * 4096 + i2;
                        bool up = ((gi & k) == 0);
                        unsigned long long a = sh[i2], c = sh[ixj];
                        if ((a > c) == up) { sh[i2] = c; sh[ixj] = a; }
                    }
                }
                __syncthreads();
            }
            for (int i = t; i < 4096; i += 1024) es[seg * 4096 + i] = sh[i];
            __syncthreads();
        }
    }

    for (int e = t; e < EPER; e += 1024) {
        unsigned long long p = es[e];
        int ou = (int)((p >> 11) & 0x3FFu) - 1;
        int ov = (int)((p >> 1) & 0x3FFu) - 1;
        out_e[(long)b * 2 * EPER + e]        = (float)ou;
        out_e[(long)b * 2 * EPER + EPER + e] = (float)ov;
        out_valid[(long)b * EPER + e]        = (float)(p & 1ull);
    }
}

// ============================================================
extern "C" void kernel_launch(void* const* d_in, const int* in_sizes, int n_in,
                              void* d_out, int out_size)
{
    const float* X    = (const float*)d_in[0];
    const void*  EI   = d_in[1];
    const float* DIST = (const float*)d_in[3];
    const float* Wq   = (const float*)d_in[5];
    const float* Wk   = (const float*)d_in[6];
    const float* Wv   = (const float*)d_in[7];
    const float* Wo   = (const float*)d_in[8];
    const float* tw   = (const float*)d_in[9];
    float* out = (float*)d_out;

    gemm_k<<<dim3(4, 128), 256>>>(X, Wq, 0, out + OFF_ENC);
    gemm_k<<<dim3(4, 128), 256>>>(X, Wk, 1, out + OFF_ENC);
    gemm_k<<<dim3(4, 128), 256>>>(X, Wv, 2, out + OFF_ENC);

    attn_kernel<<<dim3(32, 8), 256>>>(DIST);

    gemm_k<<<dim3(4, 128), 256>>>(X, Wo, 3, out + OFF_ENC);

    score_kernel<<<(BB * NN * 32) / 256, 256>>>(tw);
    topk_kernel<<<BB, NN>>>(out + OFF_PERM);
    subx_kernel<<<BB * KKP, 256>>>(out + OFF_SUBX);
    edge_kernel<<<BB, 1024>>>(EI, out + OFF_EDGE, out + OFF_VALID);
}

// round 4
// speedup vs baseline: 1.5214x; 1.5214x over previous
#include <cuda_runtime.h>

#define BB 8
#define NN 1024
#define HIDD 256
#define HEADS 8
#define DHH 32
#define EPER 16384
#define KKP 512

// ---- output layout (float32, concatenated flattened outputs) ----
#define OFF_ENC   0
#define OFF_SUBX  (BB*NN*HIDD)                       // 2097152
#define OFF_EDGE  (OFF_SUBX + BB*KKP*HIDD)           // 3145728
#define OFF_PERM  (OFF_EDGE + BB*2*EPER)             // 3407872
#define OFF_VALID (OFF_PERM + BB*KKP)                // 3411968

// ---- device scratch ----
__device__ float g_Q[BB*NN*HIDD];
__device__ float g_K[BB*NN*HIDD];
__device__ float g_V[BB*NN*HIDD];
__device__ float g_AO[BB*NN*HIDD];
__device__ float g_ENC[BB*NN*HIDD];
__device__ float g_score[BB*NN];
__device__ int   g_perm[BB*KKP];
__device__ float g_vals[BB*KKP];
__device__ int   g_nodemap[BB*NN];
__device__ unsigned long long g_es[BB*EPER];

// ---- packed f32x2 helpers ----
__device__ __forceinline__ unsigned long long fma2(
    unsigned long long a, unsigned long long b, unsigned long long c) {
    unsigned long long d;
    asm("fma.rn.f32x2 %0, %1, %2, %3;" : "=l"(d) : "l"(a), "l"(b), "l"(c));
    return d;
}
__device__ __forceinline__ unsigned long long mul2(
    unsigned long long a, unsigned long long b) {
    unsigned long long d;
    asm("mul.rn.f32x2 %0, %1, %2;" : "=l"(d) : "l"(a), "l"(b));
    return d;
}
__device__ __forceinline__ unsigned long long pack2(float lo, float hi) {
    unsigned long long r;
    asm("mov.b64 %0, {%1, %2};" : "=l"(r) : "f"(lo), "f"(hi));
    return r;
}
__device__ __forceinline__ float2 unpack2(unsigned long long v) {
    float2 r;
    asm("mov.b64 {%0, %1}, %2;" : "=f"(r.x), "=f"(r.y) : "l"(v));
    return r;
}

// ============================================================
// GEMM: C[8192,256] = A[8192,256] @ W[256,256]
// ============================================================
__global__ __launch_bounds__(256) void gemm_k(
    const float* __restrict__ Aparam, const float* __restrict__ W,
    int sel, float* __restrict__ out2)
{
    const float* A;
    float* C;
    if      (sel == 0) { A = Aparam; C = g_Q; }
    else if (sel == 1) { A = Aparam; C = g_K; }
    else if (sel == 2) { A = Aparam; C = g_V; }
    else               { A = g_AO;   C = g_ENC; }

    __shared__ float As[16][64];
    __shared__ float Ws[16][64];
    const int tx = threadIdx.x & 15;
    const int ty = threadIdx.x >> 4;
    const int rowBase = blockIdx.y * 64;
    const int colBase = blockIdx.x * 64;
    float acc[4][4];
    #pragma unroll
    for (int i = 0; i < 4; i++)
        #pragma unroll
        for (int j = 0; j < 4; j++) acc[i][j] = 0.f;

    const int t  = threadIdx.x;
    const int ar = t >> 2,  ac = (t & 3) << 2;
    const int wr = t >> 4,  wc = (t & 15) << 2;

    for (int k0 = 0; k0 < 256; k0 += 16) {
        float4 a4 = *(const float4*)(A + (rowBase + ar) * 256 + k0 + ac);
        As[ac + 0][ar] = a4.x; As[ac + 1][ar] = a4.y;
        As[ac + 2][ar] = a4.z; As[ac + 3][ar] = a4.w;
        *(float4*)(&Ws[wr][wc]) = *(const float4*)(W + (k0 + wr) * 256 + colBase + wc);
        __syncthreads();
        #pragma unroll
        for (int kk = 0; kk < 16; kk++) {
            float4 a = *(const float4*)(&As[kk][ty << 2]);
            float4 w = *(const float4*)(&Ws[kk][tx << 2]);
            acc[0][0] += a.x * w.x; acc[0][1] += a.x * w.y; acc[0][2] += a.x * w.z; acc[0][3] += a.x * w.w;
            acc[1][0] += a.y * w.x; acc[1][1] += a.y * w.y; acc[1][2] += a.y * w.z; acc[1][3] += a.y * w.w;
            acc[2][0] += a.z * w.x; acc[2][1] += a.z * w.y; acc[2][2] += a.z * w.z; acc[2][3] += a.z * w.w;
            acc[3][0] += a.w * w.x; acc[3][1] += a.w * w.y; acc[3][2] += a.w * w.z; acc[3][3] += a.w * w.w;
        }
        __syncthreads();
    }
    #pragma unroll
    for (int i = 0; i < 4; i++) {
        int row = rowBase + (ty << 2) + i;
        float4 v = make_float4(acc[i][0], acc[i][1], acc[i][2], acc[i][3]);
        *(float4*)(C + row * 256 + colBase + (tx << 2)) = v;
        if (sel == 3) *(float4*)(out2 + row * 256 + colBase + (tx << 2)) = v;
    }
}

// ============================================================
// Attention with packed f32x2 math. Block = (32-q tile, b),
// 256 thr = 8 heads x 32 q. 2 blocks/SM via launch_bounds.
// ============================================================
__global__ __launch_bounds__(256, 2) void attn_kernel(const float* __restrict__ dist)
{
    __shared__ float Ks[16 * 256];
    __shared__ float Vs[16 * 256];
    __shared__ float ds[32 * 17];

    const int b = blockIdx.y;
    const int qbase = blockIdx.x * 32;
    const int t = threadIdx.x;
    const int h = t >> 5, q = t & 31;

    // q vector as 16 packed f32x2
    unsigned long long qv2[16];
    {
        const ulonglong2* qp = (const ulonglong2*)(g_Q + ((long)(b * NN + qbase + q)) * HIDD + (h << 5));
        #pragma unroll
        for (int d4 = 0; d4 < 8; d4++) {
            ulonglong2 v = qp[d4];
            qv2[2*d4]   = v.x;
            qv2[2*d4+1] = v.y;
        }
    }

    float m = -1e30f, l = 0.f;
    unsigned long long o2[16];
    #pragma unroll
    for (int d = 0; d < 16; d++) o2[d] = 0ull;
    const float scale = 0.1767766952966369f;  // 1/sqrt(32)

    for (int kt = 0; kt < 64; kt++) {
        const int kbase = kt * 16;
        const float* Kg = g_K + ((long)(b * NN + kbase)) * HIDD;
        const float* Vg = g_V + ((long)(b * NN + kbase)) * HIDD;
        __syncthreads();
        for (int idx = t; idx < 1024; idx += 256) {
            ((float4*)Ks)[idx] = ((const float4*)Kg)[idx];
            ((float4*)Vs)[idx] = ((const float4*)Vg)[idx];
        }
        for (int idx = t; idx < 512; idx += 256) {
            int qq = idx >> 4, kk = idx & 15;
            ds[qq * 17 + kk] = dist[((long)(b * NN + qbase + qq)) * NN + kbase + kk];
        }
        __syncthreads();

        float sv[16];
        float smax = -1e30f;
        #pragma unroll
        for (int kk = 0; kk < 16; kk++) {
            const ulonglong2* kp = (const ulonglong2*)(Ks + kk * 256 + (h << 5));
            unsigned long long accA = 0ull, accB = 0ull;
            #pragma unroll
            for (int d4 = 0; d4 < 8; d4++) {
                ulonglong2 k2 = kp[d4];
                accA = fma2(qv2[2*d4],   k2.x, accA);
                accB = fma2(qv2[2*d4+1], k2.y, accB);
            }
            float2 fa = unpack2(accA), fb = unpack2(accB);
            float s = (fa.x + fa.y) + (fb.x + fb.y);
            s = s * scale + ds[q * 17 + kk];
            sv[kk] = s;
            smax = fmaxf(smax, s);
        }
        float mnew = fmaxf(m, smax);
        float corr = __expf(m - mnew);
        l *= corr;
        unsigned long long cc = pack2(corr, corr);
        #pragma unroll
        for (int d = 0; d < 16; d++) o2[d] = mul2(o2[d], cc);
        #pragma unroll
        for (int kk = 0; kk < 16; kk++) {
            float p = __expf(sv[kk] - mnew);
            l += p;
            unsigned long long pb = pack2(p, p);
            const ulonglong2* vp = (const ulonglong2*)(Vs + kk * 256 + (h << 5));
            #pragma unroll
            for (int d4 = 0; d4 < 8; d4++) {
                ulonglong2 v2 = vp[d4];
                o2[2*d4]   = fma2(v2.x, pb, o2[2*d4]);
                o2[2*d4+1] = fma2(v2.y, pb, o2[2*d4+1]);
            }
        }
        m = mnew;
    }

    float inv = 1.f / l;
    float* op = g_AO + ((long)(b * NN + qbase + q)) * HIDD + (h << 5);
    #pragma unroll
    for (int d4 = 0; d4 < 8; d4++) {
        float2 a = unpack2(o2[2*d4]), c = unpack2(o2[2*d4+1]);
        ((float4*)op)[d4] = make_float4(a.x * inv, a.y * inv, c.x * inv, c.y * inv);
    }
}

// ============================================================
// Node scores: s = tanh((x . w) / ||w||). One warp per node.
// ============================================================
__global__ __launch_bounds__(256) void score_kernel(const float* __restrict__ w)
{
    int warp = (blockIdx.x * blockDim.x + threadIdx.x) >> 5;
    int lane = threadIdx.x & 31;
    if (warp >= BB * NN) return;
    const float* x = g_ENC + (long)warp * HIDD;
    float sx = 0.f, sw = 0.f;
    #pragma unroll
    for (int i = lane; i < HIDD; i += 32) {
        float wv = w[i];
        sx += x[i] * wv;
        sw += wv * wv;
    }
    #pragma unroll
    for (int off = 16; off; off >>= 1) {
        sx += __shfl_xor_sync(0xFFFFFFFFu, sx, off);
        sw += __shfl_xor_sync(0xFFFFFFFFu, sw, off);
    }
    if (lane == 0) g_score[warp] = tanhf(sx / sqrtf(sw));
}

// ============================================================
// Top-K per graph: bitonic sort of 1024 (desc score, asc index).
// ============================================================
__global__ __launch_bounds__(1024) void topk_kernel(float* __restrict__ out_perm)
{
    __shared__ unsigned long long s[NN];
    const int b = blockIdx.x, t = threadIdx.x;
    float sc = g_score[b * NN + t];
    unsigned u = __float_as_uint(sc);
    u = (u & 0x80000000u) ? ~u : (u | 0x80000000u);
    u = ~u;                                            // descending
    s[t] = (((unsigned long long)u) << 32) | (unsigned)t;
    g_nodemap[b * NN + t] = -1;
    __syncthreads();
    for (unsigned k = 2; k <= NN; k <<= 1)
        for (unsigned j = k >> 1; j; j >>= 1) {
            unsigned i = t, ixj = i ^ j;
            if (ixj > i) {
                bool up = ((i & k) == 0);
                unsigned long long a = s[i], c = s[ixj];
                if ((a > c) == up) { s[i] = c; s[ixj] = a; }
            }
            __syncthreads();
        }
    if (t < KKP) {
        int node = (int)(s[t] & 0xFFFFFFFFu);
        g_perm[b * KKP + t] = node;
        g_vals[b * KKP + t] = g_score[b * NN + node];
        out_perm[b * KKP + t] = (float)node;
        g_nodemap[b * NN + node] = t;
    }
}

// ============================================================
// sub_x gather
// ============================================================
__global__ __launch_bounds__(256) void subx_kernel(float* __restrict__ out)
{
    const int row = blockIdx.x;
    const int b = row / KKP;
    const int node = g_perm[row];
    const float val = g_vals[row];
    const float* src = g_ENC + ((long)b * NN + node) * HIDD;
    out[(long)row * HIDD + threadIdx.x] = src[threadIdx.x] * val;
}

// ============================================================
// Edge pipeline (multi-kernel for parallelism).
// Packed: key(19b) << 21 | (ou+1)<<11 | (ov+1)<<1 | valid.
// ============================================================
__global__ __launch_bounds__(256) void edge_build(const void* __restrict__ eiraw)
{
    __shared__ int s_is64;
    if (threadIdx.x == 0) {
        const unsigned* w32 = (const unsigned*)eiraw;
        int all0 = 1;
        for (int i = 0; i < 64; i++)
            if (w32[2 * i + 1] != 0u) { all0 = 0; break; }
        s_is64 = all0;
    }
    __syncthreads();
    const int is64 = s_is64;
    const int total = BB * EPER;
    for (int idx = blockIdx.x * blockDim.x + threadIdx.x; idx < total;
         idx += gridDim.x * blockDim.x) {
        int b = idx >> 14;
        long long vs, vd;
        if (is64) {
            const long long* ei = (const long long*)eiraw;
            vs = ei[idx];
            vd = ei[total + idx];
        } else {
            const int* ei = (const int*)eiraw;
            vs = ei[idx];
            vd = ei[total + idx];
        }
        int src = (int)(vs - (long long)b * NN);
        int dst = (int)(vd - (long long)b * NN);
        src = min(max(src, 0), NN - 1);
        dst = min(max(dst, 0), NN - 1);
        int nu = g_nodemap[b * NN + src];
        int nv = g_nodemap[b * NN + dst];
        bool valid = (nu >= 0) && (nv >= 0);
        unsigned key = valid ? (unsigned)(nu * KKP + nv) : (unsigned)(KKP * KKP);
        int ou = valid ? nu : -1, ov = valid ? nv : -1;
        g_es[idx] = (((unsigned long long)key) << 21)
                  | (((unsigned long long)(ou + 1)) << 11)
                  | (((unsigned long long)(ov + 1)) << 1)
                  | (valid ? 1ull : 0ull);
    }
}

// Fully sort each 4096-segment in shared (direction from global index).
__global__ __launch_bounds__(1024) void edge_sort_seg()
{
    __shared__ unsigned long long sh[4096];
    const int b = blockIdx.x >> 2, seg = blockIdx.x & 3;
    const int t = threadIdx.x;
    unsigned long long* es = g_es + (long)b * EPER + seg * 4096;
    for (int i = t; i < 4096; i += 1024) sh[i] = es[i];
    __syncthreads();
    for (unsigned k = 2; k <= 4096; k <<= 1)
        for (unsigned j = k >> 1; j; j >>= 1) {
            for (int loc = t; loc < 4096; loc += 1024) {
                unsigned i2 = (unsigned)loc, ixj = i2 ^ j;
                if (ixj > i2) {
                    unsigned gi = seg * 4096 + i2;
                    bool up = ((gi & k) == 0);
                    unsigned long long a = sh[i2], c = sh[ixj];
                    if ((a > c) == up) { sh[i2] = c; sh[ixj] = a; }
                }
            }
            __syncthreads();
        }
    for (int i = t; i < 4096; i += 1024) es[i] = sh[i];
}

// One global bitonic step (k, j >= 4096), grid covers all B*EPER elements.
__global__ __launch_bounds__(1024) void edge_gmerge(unsigned k, unsigned j)
{
    int loc = blockIdx.x * blockDim.x + threadIdx.x;   // 0 .. B*EPER-1
    unsigned i = (unsigned)(loc & (EPER - 1));
    int b = loc >> 14;
    unsigned ixj = i ^ j;
    if (ixj > i) {
        unsigned long long* es = g_es + (long)b * EPER;
        bool up = ((i & k) == 0);
        unsigned long long a = es[i], c = es[ixj];
        if ((a > c) == up) { es[i] = c; es[ixj] = a; }
    }
}

// Shared-memory merge tail (j = 2048 .. 1) for a given k.
__global__ __launch_bounds__(1024) void edge_smerge(unsigned k)
{
    __shared__ unsigned long long sh[4096];
    const int b = blockIdx.x >> 2, seg = blockIdx.x & 3;
    const int t = threadIdx.x;
    unsigned long long* es = g_es + (long)b * EPER + seg * 4096;
    for (int i = t; i < 4096; i += 1024) sh[i] = es[i];
    __syncthreads();
    for (unsigned j = 2048; j; j >>= 1) {
        for (int loc = t; loc < 4096; loc += 1024) {
            unsigned i2 = (unsigned)loc, ixj = i2 ^ j;
            if (ixj > i2) {
                unsigned gi = seg * 4096 + i2;
                bool up = ((gi & k) == 0);
                unsigned long long a = sh[i2], c = sh[ixj];
                if ((a > c) == up) { sh[i2] = c; sh[ixj] = a; }
            }
        }
        __syncthreads();
    }
    for (int i = t; i < 4096; i += 1024) es[i] = sh[i];
}

__global__ __launch_bounds__(256) void edge_emit(
    float* __restrict__ out_e, float* __restrict__ out_valid)
{
    const int total = BB * EPER;
    for (int idx = blockIdx.x * blockDim.x + threadIdx.x; idx < total;
         idx += gridDim.x * blockDim.x) {
        int b = idx >> 14, e = idx & (EPER - 1);
        unsigned long long p = g_es[idx];
        int ou = (int)((p >> 11) & 0x3FFu) - 1;
        int ov = (int)((p >> 1) & 0x3FFu) - 1;
        out_e[(long)b * 2 * EPER + e]        = (float)ou;
        out_e[(long)b * 2 * EPER + EPER + e] = (float)ov;
        out_valid[(long)b * EPER + e]        = (float)(p & 1ull);
    }
}

// ============================================================
extern "C" void kernel_launch(void* const* d_in, const int* in_sizes, int n_in,
                              void* d_out, int out_size)
{
    const float* X    = (const float*)d_in[0];
    const void*  EI   = d_in[1];
    const float* DIST = (const float*)d_in[3];
    const float* Wq   = (const float*)d_in[5];
    const float* Wk   = (const float*)d_in[6];
    const float* Wv   = (const float*)d_in[7];
    const float* Wo   = (const float*)d_in[8];
    const float* tw   = (const float*)d_in[9];
    float* out = (float*)d_out;

    gemm_k<<<dim3(4, 128), 256>>>(X, Wq, 0, out + OFF_ENC);
    gemm_k<<<dim3(4, 128), 256>>>(X, Wk, 1, out + OFF_ENC);
    gemm_k<<<dim3(4, 128), 256>>>(X, Wv, 2, out + OFF_ENC);

    attn_kernel<<<dim3(32, 8), 256>>>(DIST);

    gemm_k<<<dim3(4, 128), 256>>>(X, Wo, 3, out + OFF_ENC);

    score_kernel<<<(BB * NN * 32) / 256, 256>>>(tw);
    topk_kernel<<<BB, NN>>>(out + OFF_PERM);
    subx_kernel<<<BB * KKP, 256>>>(out + OFF_SUBX);

    edge_build<<<128, 256>>>(EI);
    edge_sort_seg<<<32, 1024>>>();
    edge_gmerge<<<128, 1024>>>(8192u, 4096u);
    edge_smerge<<<32, 1024>>>(8192u);
    edge_gmerge<<<128, 1024>>>(16384u, 8192u);
    edge_gmerge<<<128, 1024>>>(16384u, 4096u);
    edge_smerge<<<32, 1024>>>(16384u);
    edge_emit<<<128, 256>>>(out + OFF_EDGE, out + OFF_VALID);
}

// round 5
// speedup vs baseline: 1.6311x; 1.0721x over previous
#include <cuda_runtime.h>

#define BB 8
#define NN 1024
#define HIDD 256
#define HEADS 8
#define DHH 32
#define EPER 16384
#define KKP 512

// ---- output layout (float32, concatenated flattened outputs) ----
#define OFF_ENC   0
#define OFF_SUBX  (BB*NN*HIDD)
#define OFF_EDGE  (OFF_SUBX + BB*KKP*HIDD)
#define OFF_PERM  (OFF_EDGE + BB*2*EPER)
#define OFF_VALID (OFF_PERM + BB*KKP)

// ---- device scratch ----
__device__ float g_Q[BB*NN*HIDD];
__device__ float g_K[BB*NN*HIDD];
__device__ float g_V[BB*NN*HIDD];
__device__ float g_AO[BB*NN*HIDD];
__device__ float g_ENC[BB*NN*HIDD];
__device__ float g_score[BB*NN];
__device__ int   g_perm[BB*KKP];
__device__ float g_vals[BB*KKP];
__device__ int   g_nodemap[BB*NN];
__device__ unsigned long long g_es[BB*EPER];

// ---- packed f32x2 helpers ----
__device__ __forceinline__ unsigned long long fma2(
    unsigned long long a, unsigned long long b, unsigned long long c) {
    unsigned long long d;
    asm("fma.rn.f32x2 %0, %1, %2, %3;" : "=l"(d) : "l"(a), "l"(b), "l"(c));
    return d;
}
__device__ __forceinline__ unsigned long long mul2(
    unsigned long long a, unsigned long long b) {
    unsigned long long d;
    asm("mul.rn.f32x2 %0, %1, %2;" : "=l"(d) : "l"(a), "l"(b));
    return d;
}
__device__ __forceinline__ unsigned long long pack2(float lo, float hi) {
    unsigned long long r;
    asm("mov.b64 %0, {%1, %2};" : "=l"(r) : "f"(lo), "f"(hi));
    return r;
}
__device__ __forceinline__ float2 unpack2(unsigned long long v) {
    float2 r;
    asm("mov.b64 {%0, %1}, %2;" : "=f"(r.x), "=f"(r.y) : "l"(v));
    return r;
}

// ============================================================
// GEMM (f32x2 microtile): C[8192,256] = A[8192,256] @ W[256,256]
// ============================================================
__global__ __launch_bounds__(256) void gemm_k(
    const float* __restrict__ Aparam, const float* __restrict__ W,
    int sel, float* __restrict__ out2)
{
    const float* A;
    float* C;
    if      (sel == 0) { A = Aparam; C = g_Q; }
    else if (sel == 1) { A = Aparam; C = g_K; }
    else if (sel == 2) { A = Aparam; C = g_V; }
    else               { A = g_AO;   C = g_ENC; }

    __shared__ float As[16][64];
    __shared__ float Ws[16][64];
    const int tx = threadIdx.x & 15;
    const int ty = threadIdx.x >> 4;
    const int rowBase = blockIdx.y * 64;
    const int colBase = blockIdx.x * 64;

    unsigned long long acc2[4][2];
    #pragma unroll
    for (int i = 0; i < 4; i++) { acc2[i][0] = 0ull; acc2[i][1] = 0ull; }

    const int t  = threadIdx.x;
    const int ar = t >> 2,  ac = (t & 3) << 2;
    const int wr = t >> 4,  wc = (t & 15) << 2;

    for (int k0 = 0; k0 < 256; k0 += 16) {
        float4 a4 = *(const float4*)(A + (rowBase + ar) * 256 + k0 + ac);
        As[ac + 0][ar] = a4.x; As[ac + 1][ar] = a4.y;
        As[ac + 2][ar] = a4.z; As[ac + 3][ar] = a4.w;
        *(float4*)(&Ws[wr][wc]) = *(const float4*)(W + (k0 + wr) * 256 + colBase + wc);
        __syncthreads();
        #pragma unroll
        for (int kk = 0; kk < 16; kk++) {
            float4 a = *(const float4*)(&As[kk][ty << 2]);
            ulonglong2 w2 = *(const ulonglong2*)(&Ws[kk][tx << 2]);
            unsigned long long a0 = pack2(a.x, a.x), a1 = pack2(a.y, a.y);
            unsigned long long a2 = pack2(a.z, a.z), a3 = pack2(a.w, a.w);
            acc2[0][0] = fma2(a0, w2.x, acc2[0][0]); acc2[0][1] = fma2(a0, w2.y, acc2[0][1]);
            acc2[1][0] = fma2(a1, w2.x, acc2[1][0]); acc2[1][1] = fma2(a1, w2.y, acc2[1][1]);
            acc2[2][0] = fma2(a2, w2.x, acc2[2][0]); acc2[2][1] = fma2(a2, w2.y, acc2[2][1]);
            acc2[3][0] = fma2(a3, w2.x, acc2[3][0]); acc2[3][1] = fma2(a3, w2.y, acc2[3][1]);
        }
        __syncthreads();
    }
    #pragma unroll
    for (int i = 0; i < 4; i++) {
        int row = rowBase + (ty << 2) + i;
        float2 lo = unpack2(acc2[i][0]), hi = unpack2(acc2[i][1]);
        float4 v = make_float4(lo.x, lo.y, hi.x, hi.y);
        *(float4*)(C + row * 256 + colBase + (tx << 2)) = v;
        if (sel == 3) *(float4*)(out2 + row * 256 + colBase + (tx << 2)) = v;
    }
}

// ============================================================
// Attention: software-pipelined, k-tile 8 double-buffered,
// f32x2 math, rescale elision. Block = (32-q tile, b),
// 256 thr = 8 heads x 32 q, 2 blocks/SM.
// ============================================================
__global__ __launch_bounds__(256, 2) void attn_kernel(const float* __restrict__ dist)
{
    __shared__ float Ks[2][8 * 256];
    __shared__ float Vs[2][8 * 256];
    __shared__ float ds[2][32 * 9];

    const int b = blockIdx.y;
    const int qbase = blockIdx.x * 32;
    const int t = threadIdx.x;
    const int h = t >> 5, q = t & 31;
    const int drow = t >> 3, dcol = t & 7;

    const float* Kg = g_K + (long)b * NN * HIDD;
    const float* Vg = g_V + (long)b * NN * HIDD;
    const float* dg = dist + ((long)(b * NN + qbase + drow)) * NN + dcol;

    // q vector as 16 packed f32x2
    unsigned long long qv2[16];
    {
        const ulonglong2* qp = (const ulonglong2*)(g_Q + ((long)(b * NN + qbase + q)) * HIDD + (h << 5));
        #pragma unroll
        for (int d4 = 0; d4 < 8; d4++) {
            ulonglong2 v = qp[d4];
            qv2[2*d4]   = v.x;
            qv2[2*d4+1] = v.y;
        }
    }

    // preload tile 0 directly into buffer 0
    {
        const float4* K0 = (const float4*)Kg;
        const float4* V0 = (const float4*)Vg;
        ((float4*)Ks[0])[t]       = K0[t];
        ((float4*)Ks[0])[t + 256] = K0[t + 256];
        ((float4*)Vs[0])[t]       = V0[t];
        ((float4*)Vs[0])[t + 256] = V0[t + 256];
        ds[0][drow * 9 + dcol] = dg[0];
    }
    __syncthreads();

    float m = -1e30f, l = 0.f;
    unsigned long long o2[16];
    #pragma unroll
    for (int d = 0; d < 16; d++) o2[d] = 0ull;
    const float scale = 0.1767766952966369f;  // 1/sqrt(32)

    for (int kt = 0; kt < 128; kt++) {
        const int cur = kt & 1;
        float4 pk0, pk1, pv0, pv1; float pd;
        if (kt < 127) {   // prefetch next tile into registers
            const float4* Kn = (const float4*)Kg + (kt + 1) * 512;
            const float4* Vn = (const float4*)Vg + (kt + 1) * 512;
            pk0 = Kn[t]; pk1 = Kn[t + 256];
            pv0 = Vn[t]; pv1 = Vn[t + 256];
            pd  = dg[(kt + 1) * 8];
        }

        const float* Kc = Ks[cur];
        const float* Vc = Vs[cur];
        const float* dc = ds[cur] + q * 9;

        float sv[8];
        float smax = -1e30f;
        #pragma unroll
        for (int kk = 0; kk < 8; kk++) {
            const ulonglong2* kp = (const ulonglong2*)(Kc + kk * 256 + (h << 5));
            unsigned long long accA = 0ull, accB = 0ull;
            #pragma unroll
            for (int d4 = 0; d4 < 8; d4++) {
                ulonglong2 k2 = kp[d4];
                accA = fma2(qv2[2*d4],   k2.x, accA);
                accB = fma2(qv2[2*d4+1], k2.y, accB);
            }
            float2 fa = unpack2(accA), fb = unpack2(accB);
            float s = (fa.x + fa.y) + (fb.x + fb.y);
            s = s * scale + dc[kk];
            sv[kk] = s;
            smax = fmaxf(smax, s);
        }
        float mnew = fmaxf(m, smax);
        if (__any_sync(0xFFFFFFFFu, mnew > m)) {
            float corr = __expf(m - mnew);
            l *= corr;
            unsigned long long cc = pack2(corr, corr);
            #pragma unroll
            for (int d = 0; d < 16; d++) o2[d] = mul2(o2[d], cc);
            m = mnew;
        }
        #pragma unroll
        for (int kk = 0; kk < 8; kk++) {
            float p = __expf(sv[kk] - m);
            l += p;
            unsigned long long pb = pack2(p, p);
            const ulonglong2* vp = (const ulonglong2*)(Vc + kk * 256 + (h << 5));
            #pragma unroll
            for (int d4 = 0; d4 < 8; d4++) {
                ulonglong2 v2 = vp[d4];
                o2[2*d4]   = fma2(v2.x, pb, o2[2*d4]);
                o2[2*d4+1] = fma2(v2.y, pb, o2[2*d4+1]);
            }
        }

        if (kt < 127) {   // store prefetched tile to alternate buffer
            const int nxt = cur ^ 1;
            ((float4*)Ks[nxt])[t]       = pk0;
            ((float4*)Ks[nxt])[t + 256] = pk1;
            ((float4*)Vs[nxt])[t]       = pv0;
            ((float4*)Vs[nxt])[t + 256] = pv1;
            ds[nxt][drow * 9 + dcol] = pd;
        }
        __syncthreads();
    }

    float inv = 1.f / l;
    float* op = g_AO + ((long)(b * NN + qbase + q)) * HIDD + (h << 5);
    #pragma unroll
    for (int d4 = 0; d4 < 8; d4++) {
        float2 a = unpack2(o2[2*d4]), c = unpack2(o2[2*d4+1]);
        ((float4*)op)[d4] = make_float4(a.x * inv, a.y * inv, c.x * inv, c.y * inv);
    }
}

// ============================================================
// Node scores: s = tanh((x . w) / ||w||). One warp per node.
// ============================================================
__global__ __launch_bounds__(256) void score_kernel(const float* __restrict__ w)
{
    int warp = (blockIdx.x * blockDim.x + threadIdx.x) >> 5;
    int lane = threadIdx.x & 31;
    if (warp >= BB * NN) return;
    const float* x = g_ENC + (long)warp * HIDD;
    float sx = 0.f, sw = 0.f;
    #pragma unroll
    for (int i = lane; i < HIDD; i += 32) {
        float wv = w[i];
        sx += x[i] * wv;
        sw += wv * wv;
    }
    #pragma unroll
    for (int off = 16; off; off >>= 1) {
        sx += __shfl_xor_sync(0xFFFFFFFFu, sx, off);
        sw += __shfl_xor_sync(0xFFFFFFFFu, sw, off);
    }
    if (lane == 0) g_score[warp] = tanhf(sx / sqrtf(sw));
}

// ============================================================
// Top-K per graph: bitonic sort of 1024 (desc score, asc index).
// ============================================================
__global__ __launch_bounds__(1024) void topk_kernel(float* __restrict__ out_perm)
{
    __shared__ unsigned long long s[NN];
    const int b = blockIdx.x, t = threadIdx.x;
    float sc = g_score[b * NN + t];
    unsigned u = __float_as_uint(sc);
    u = (u & 0x80000000u) ? ~u : (u | 0x80000000u);
    u = ~u;                                            // descending
    s[t] = (((unsigned long long)u) << 32) | (unsigned)t;
    g_nodemap[b * NN + t] = -1;
    __syncthreads();
    for (unsigned k = 2; k <= NN; k <<= 1)
        for (unsigned j = k >> 1; j; j >>= 1) {
            unsigned i = t, ixj = i ^ j;
            if (ixj > i) {
                bool up = ((i & k) == 0);
                unsigned long long a = s[i], c = s[ixj];
                if ((a > c) == up) { s[i] = c; s[ixj] = a; }
            }
            __syncthreads();
        }
    if (t < KKP) {
        int node = (int)(s[t] & 0xFFFFFFFFu);
        g_perm[b * KKP + t] = node;
        g_vals[b * KKP + t] = g_score[b * NN + node];
        out_perm[b * KKP + t] = (float)node;
        g_nodemap[b * NN + node] = t;
    }
}

// ============================================================
// sub_x gather
// ============================================================
__global__ __launch_bounds__(256) void subx_kernel(float* __restrict__ out)
{
    const int row = blockIdx.x;
    const int b = row / KKP;
    const int node = g_perm[row];
    const float val = g_vals[row];
    const float* src = g_ENC + ((long)b * NN + node) * HIDD;
    out[(long)row * HIDD + threadIdx.x] = src[threadIdx.x] * val;
}

// ============================================================
// Edge pipeline (multi-kernel bitonic).
// ============================================================
__global__ __launch_bounds__(256) void edge_build(const void* __restrict__ eiraw)
{
    __shared__ int s_is64;
    if (threadIdx.x == 0) {
        const unsigned* w32 = (const unsigned*)eiraw;
        int all0 = 1;
        for (int i = 0; i < 64; i++)
            if (w32[2 * i + 1] != 0u) { all0 = 0; break; }
        s_is64 = all0;
    }
    __syncthreads();
    const int is64 = s_is64;
    const int total = BB * EPER;
    for (int idx = blockIdx.x * blockDim.x + threadIdx.x; idx < total;
         idx += gridDim.x * blockDim.x) {
        int b = idx >> 14;
        long long vs, vd;
        if (is64) {
            const long long* ei = (const long long*)eiraw;
            vs = ei[idx];
            vd = ei[total + idx];
        } else {
            const int* ei = (const int*)eiraw;
            vs = ei[idx];
            vd = ei[total + idx];
        }
        int src = (int)(vs - (long long)b * NN);
        int dst = (int)(vd - (long long)b * NN);
        src = min(max(src, 0), NN - 1);
        dst = min(max(dst, 0), NN - 1);
        int nu = g_nodemap[b * NN + src];
        int nv = g_nodemap[b * NN + dst];
        bool valid = (nu >= 0) && (nv >= 0);
        unsigned key = valid ? (unsigned)(nu * KKP + nv) : (unsigned)(KKP * KKP);
        int ou = valid ? nu : -1, ov = valid ? nv : -1;
        g_es[idx] = (((unsigned long long)key) << 21)
                  | (((unsigned long long)(ou + 1)) << 11)
                  | (((unsigned long long)(ov + 1)) << 1)
                  | (valid ? 1ull : 0ull);
    }
}

__global__ __launch_bounds__(1024) void edge_sort_seg()
{
    __shared__ unsigned long long sh[4096];
    const int b = blockIdx.x >> 2, seg = blockIdx.x & 3;
    const int t = threadIdx.x;
    unsigned long long* es = g_es + (long)b * EPER + seg * 4096;
    for (int i = t; i < 4096; i += 1024) sh[i] = es[i];
    __syncthreads();
    for (unsigned k = 2; k <= 4096; k <<= 1)
        for (unsigned j = k >> 1; j; j >>= 1) {
            for (int loc = t; loc < 4096; loc += 1024) {
                unsigned i2 = (unsigned)loc, ixj = i2 ^ j;
                if (ixj > i2) {
                    unsigned gi = seg * 4096 + i2;
                    bool up = ((gi & k) == 0);
                    unsigned long long a = sh[i2], c = sh[ixj];
                    if ((a > c) == up) { sh[i2] = c; sh[ixj] = a; }
                }
            }
            __syncthreads();
        }
    for (int i = t; i < 4096; i += 1024) es[i] = sh[i];
}

__global__ __launch_bounds__(1024) void edge_gmerge(unsigned k, unsigned j)
{
    int loc = blockIdx.x * blockDim.x + threadIdx.x;
    unsigned i = (unsigned)(loc & (EPER - 1));
    int b = loc >> 14;
    unsigned ixj = i ^ j;
    if (ixj > i) {
        unsigned long long* es = g_es + (long)b * EPER;
        bool up = ((i & k) == 0);
        unsigned long long a = es[i], c = es[ixj];
        if ((a > c) == up) { es[i] = c; es[ixj] = a; }
    }
}

__global__ __launch_bounds__(1024) void edge_smerge(unsigned k)
{
    __shared__ unsigned long long sh[4096];
    const int b = blockIdx.x >> 2, seg = blockIdx.x & 3;
    const int t = threadIdx.x;
    unsigned long long* es = g_es + (long)b * EPER + seg * 4096;
    for (int i = t; i < 4096; i += 1024) sh[i] = es[i];
    __syncthreads();
    for (unsigned j = 2048; j; j >>= 1) {
        for (int loc = t; loc < 4096; loc += 1024) {
            unsigned i2 = (unsigned)loc, ixj = i2 ^ j;
            if (ixj > i2) {
                unsigned gi = seg * 4096 + i2;
                bool up = ((gi & k) == 0);
                unsigned long long a = sh[i2], c = sh[ixj];
                if ((a > c) == up) { sh[i2] = c; sh[ixj] = a; }
            }
        }
        __syncthreads();
    }
    for (int i = t; i < 4096; i += 1024) es[i] = sh[i];
}

__global__ __launch_bounds__(256) void edge_emit(
    float* __restrict__ out_e, float* __restrict__ out_valid)
{
    const int total = BB * EPER;
    for (int idx = blockIdx.x * blockDim.x + threadIdx.x; idx < total;
         idx += gridDim.x * blockDim.x) {
        int b = idx >> 14, e = idx & (EPER - 1);
        unsigned long long p = g_es[idx];
        int ou = (int)((p >> 11) & 0x3FFu) - 1;
        int ov = (int)((p >> 1) & 0x3FFu) - 1;
        out_e[(long)b * 2 * EPER + e]        = (float)ou;
        out_e[(long)b * 2 * EPER + EPER + e] = (float)ov;
        out_valid[(long)b * EPER + e]        = (float)(p & 1ull);
    }
}

// ============================================================
extern "C" void kernel_launch(void* const* d_in, const int* in_sizes, int n_in,
                              void* d_out, int out_size)
{
    const float* X    = (const float*)d_in[0];
    const void*  EI   = d_in[1];
    const float* DIST = (const float*)d_in[3];
    const float* Wq   = (const float*)d_in[5];
    const float* Wk   = (const float*)d_in[6];
    const float* Wv   = (const float*)d_in[7];
    const float* Wo   = (const float*)d_in[8];
    const float* tw   = (const float*)d_in[9];
    float* out = (float*)d_out;

    gemm_k<<<dim3(4, 128), 256>>>(X, Wq, 0, out + OFF_ENC);
    gemm_k<<<dim3(4, 128), 256>>>(X, Wk, 1, out + OFF_ENC);
    gemm_k<<<dim3(4, 128), 256>>>(X, Wv, 2, out + OFF_ENC);

    attn_kernel<<<dim3(32, 8), 256>>>(DIST);

    gemm_k<<<dim3(4, 128), 256>>>(X, Wo, 3, out + OFF_ENC);

    score_kernel<<<(BB * NN * 32) / 256, 256>>>(tw);
    topk_kernel<<<BB, NN>>>(out + OFF_PERM);
    subx_kernel<<<BB * KKP, 256>>>(out + OFF_SUBX);

    edge_build<<<128, 256>>>(EI);
    edge_sort_seg<<<32, 1024>>>();
    edge_gmerge<<<128, 1024>>>(8192u, 4096u);
    edge_smerge<<<32, 1024>>>(8192u);
    edge_gmerge<<<128, 1024>>>(16384u, 8192u);
    edge_gmerge<<<128, 1024>>>(16384u, 4096u);
    edge_smerge<<<32, 1024>>>(16384u);
    edge_emit<<<128, 256>>>(out + OFF_EDGE, out + OFF_VALID);
}

// round 6
// speedup vs baseline: 1.9556x; 1.1990x over previous
#include <cuda_runtime.h>

#define BB 8
#define NN 1024
#define HIDD 256
#define HEADS 8
#define DHH 32
#define EPER 16384
#define KKP 512

// ---- output layout (float32, concatenated flattened outputs) ----
#define OFF_ENC   0
#define OFF_SUBX  (BB*NN*HIDD)
#define OFF_EDGE  (OFF_SUBX + BB*KKP*HIDD)
#define OFF_PERM  (OFF_EDGE + BB*2*EPER)
#define OFF_VALID (OFF_PERM + BB*KKP)

// ---- device scratch ----
__device__ float g_Q[BB*NN*HIDD];
__device__ float g_K[BB*NN*HIDD];
__device__ float g_V[BB*NN*HIDD];
__device__ float g_AO[BB*NN*HIDD];
__device__ float g_ENC[BB*NN*HIDD];
__device__ float g_score[BB*NN];
__device__ int   g_perm[BB*KKP];
__device__ float g_vals[BB*KKP];
__device__ int   g_nodemap[BB*NN];
__device__ unsigned long long g_es[BB*EPER];

// ---- packed f32x2 helpers ----
__device__ __forceinline__ unsigned long long fma2(
    unsigned long long a, unsigned long long b, unsigned long long c) {
    unsigned long long d;
    asm("fma.rn.f32x2 %0, %1, %2, %3;" : "=l"(d) : "l"(a), "l"(b), "l"(c));
    return d;
}
__device__ __forceinline__ unsigned long long mul2(
    unsigned long long a, unsigned long long b) {
    unsigned long long d;
    asm("mul.rn.f32x2 %0, %1, %2;" : "=l"(d) : "l"(a), "l"(b));
    return d;
}
__device__ __forceinline__ unsigned long long pack2(float lo, float hi) {
    unsigned long long r;
    asm("mov.b64 %0, {%1, %2};" : "=l"(r) : "f"(lo), "f"(hi));
    return r;
}
__device__ __forceinline__ float2 unpack2(unsigned long long v) {
    float2 r;
    asm("mov.b64 {%0, %1}, %2;" : "=f"(r.x), "=f"(r.y) : "l"(v));
    return r;
}

// ============================================================
// GEMM: C[8192,256] = A[8192,256] @ W[256,256]
// 128x64 block tile, 256 threads, 8x4 microtile (f32x2), K-chunk 16.
// ============================================================
__global__ __launch_bounds__(256) void gemm_k(
    const float* __restrict__ Aparam, const float* __restrict__ W,
    int sel, float* __restrict__ out2)
{
    const float* A;
    float* C;
    if      (sel == 0) { A = Aparam; C = g_Q; }
    else if (sel == 1) { A = Aparam; C = g_K; }
    else if (sel == 2) { A = Aparam; C = g_V; }
    else               { A = g_AO;   C = g_ENC; }

    __shared__ float As[16][128];
    __shared__ float Ws[16][64];
    const int t  = threadIdx.x;
    const int tx = t & 15;          // 16 col groups * 4 cols
    const int ty = t >> 4;          // 16 row groups * 8 rows
    const int rowBase = blockIdx.y * 128;
    const int colBase = blockIdx.x * 64;

    unsigned long long acc2[8][2];
    #pragma unroll
    for (int i = 0; i < 8; i++) { acc2[i][0] = 0ull; acc2[i][1] = 0ull; }

    const int wr = t >> 4, wc = (t & 15) << 2;

    for (int k0 = 0; k0 < 256; k0 += 16) {
        #pragma unroll
        for (int li = 0; li < 2; li++) {
            int idx = t * 2 + li;           // 0..511
            int row = idx >> 2;             // 0..127
            int c4  = (idx & 3) << 2;       // 0,4,8,12
            float4 a4 = *(const float4*)(A + (rowBase + row) * 256 + k0 + c4);
            As[c4 + 0][row] = a4.x; As[c4 + 1][row] = a4.y;
            As[c4 + 2][row] = a4.z; As[c4 + 3][row] = a4.w;
        }
        *(float4*)(&Ws[wr][wc]) = *(const float4*)(W + (k0 + wr) * 256 + colBase + wc);
        __syncthreads();
        #pragma unroll
        for (int kk = 0; kk < 16; kk++) {
            float4 a0 = *(const float4*)(&As[kk][ty << 3]);
            float4 a1 = *(const float4*)(&As[kk][(ty << 3) + 4]);
            ulonglong2 w2 = *(const ulonglong2*)(&Ws[kk][tx << 2]);
            unsigned long long b0 = pack2(a0.x, a0.x), b1 = pack2(a0.y, a0.y);
            unsigned long long b2 = pack2(a0.z, a0.z), b3 = pack2(a0.w, a0.w);
            unsigned long long b4 = pack2(a1.x, a1.x), b5 = pack2(a1.y, a1.y);
            unsigned long long b6 = pack2(a1.z, a1.z), b7 = pack2(a1.w, a1.w);
            acc2[0][0] = fma2(b0, w2.x, acc2[0][0]); acc2[0][1] = fma2(b0, w2.y, acc2[0][1]);
            acc2[1][0] = fma2(b1, w2.x, acc2[1][0]); acc2[1][1] = fma2(b1, w2.y, acc2[1][1]);
            acc2[2][0] = fma2(b2, w2.x, acc2[2][0]); acc2[2][1] = fma2(b2, w2.y, acc2[2][1]);
            acc2[3][0] = fma2(b3, w2.x, acc2[3][0]); acc2[3][1] = fma2(b3, w2.y, acc2[3][1]);
            acc2[4][0] = fma2(b4, w2.x, acc2[4][0]); acc2[4][1] = fma2(b4, w2.y, acc2[4][1]);
            acc2[5][0] = fma2(b5, w2.x, acc2[5][0]); acc2[5][1] = fma2(b5, w2.y, acc2[5][1]);
            acc2[6][0] = fma2(b6, w2.x, acc2[6][0]); acc2[6][1] = fma2(b6, w2.y, acc2[6][1]);
            acc2[7][0] = fma2(b7, w2.x, acc2[7][0]); acc2[7][1] = fma2(b7, w2.y, acc2[7][1]);
        }
        __syncthreads();
    }
    #pragma unroll
    for (int i = 0; i < 8; i++) {
        int row = rowBase + (ty << 3) + i;
        float2 lo = unpack2(acc2[i][0]), hi = unpack2(acc2[i][1]);
        float4 v = make_float4(lo.x, lo.y, hi.x, hi.y);
        *(float4*)(C + row * 256 + colBase + (tx << 2)) = v;
        if (sel == 3) *(float4*)(out2 + row * 256 + colBase + (tx << 2)) = v;
    }
}

// ============================================================
// Attention: 2 queries per thread (64-q tile), k-tile 8 double-
// buffered, f32x2 math, rescale elision. 256 thr = 8h x 32 lanes.
// ============================================================
__global__ __launch_bounds__(256, 1) void attn_kernel(const float* __restrict__ dist)
{
    __shared__ float Ks[2][8 * 256];
    __shared__ float Vs[2][8 * 256];
    __shared__ float ds[2][64 * 10];

    const int b = blockIdx.y;
    const int qbase = blockIdx.x * 64;
    const int t = threadIdx.x;
    const int h = t >> 5, q = t & 31;          // q0 = q, q1 = q + 32
    const int drow = t >> 2, dcol = (t & 3) << 1;  // 64 rows x 8 cols, float2

    const float* Kg = g_K + (long)b * NN * HIDD;
    const float* Vg = g_V + (long)b * NN * HIDD;
    const float* dg = dist + ((long)(b * NN + qbase + drow)) * NN + dcol;

    unsigned long long qa[16], qb[16];
    {
        const ulonglong2* qp0 = (const ulonglong2*)(g_Q + ((long)(b * NN + qbase + q)) * HIDD + (h << 5));
        const ulonglong2* qp1 = (const ulonglong2*)(g_Q + ((long)(b * NN + qbase + q + 32)) * HIDD + (h << 5));
        #pragma unroll
        for (int d4 = 0; d4 < 8; d4++) {
            ulonglong2 v0 = qp0[d4], v1 = qp1[d4];
            qa[2*d4] = v0.x; qa[2*d4+1] = v0.y;
            qb[2*d4] = v1.x; qb[2*d4+1] = v1.y;
        }
    }

    // preload tile 0
    {
        const float4* K0 = (const float4*)Kg;
        const float4* V0 = (const float4*)Vg;
        ((float4*)Ks[0])[t]       = K0[t];
        ((float4*)Ks[0])[t + 256] = K0[t + 256];
        ((float4*)Vs[0])[t]       = V0[t];
        ((float4*)Vs[0])[t + 256] = V0[t + 256];
        *(float2*)(&ds[0][drow * 10 + dcol]) = *(const float2*)dg;
    }
    __syncthreads();

    float ma = -1e30f, la = 0.f, mb = -1e30f, lb = 0.f;
    unsigned long long oa[16], ob[16];
    #pragma unroll
    for (int d = 0; d < 16; d++) { oa[d] = 0ull; ob[d] = 0ull; }
    const float scale = 0.1767766952966369f;  // 1/sqrt(32)

    for (int kt = 0; kt < 128; kt++) {
        const int cur = kt & 1;
        float4 pk0, pk1, pv0, pv1; float2 pd;
        if (kt < 127) {
            const float4* Kn = (const float4*)Kg + (kt + 1) * 512;
            const float4* Vn = (const float4*)Vg + (kt + 1) * 512;
            pk0 = Kn[t]; pk1 = Kn[t + 256];
            pv0 = Vn[t]; pv1 = Vn[t + 256];
            pd  = *(const float2*)(dg + (kt + 1) * 8);
        }

        const float* Kc = Ks[cur];
        const float* Vc = Vs[cur];
        const float* dA = &ds[cur][q * 10];
        const float* dB = &ds[cur][(q + 32) * 10];

        float sva[8], svb[8];
        float smaxa = -1e30f, smaxb = -1e30f;
        #pragma unroll
        for (int kk = 0; kk < 8; kk++) {
            const ulonglong2* kp = (const ulonglong2*)(Kc + kk * 256 + (h << 5));
            unsigned long long accA = 0ull, accB = 0ull, accC = 0ull, accD = 0ull;
            #pragma unroll
            for (int d4 = 0; d4 < 8; d4++) {
                ulonglong2 k2 = kp[d4];
                accA = fma2(qa[2*d4],   k2.x, accA);
                accB = fma2(qa[2*d4+1], k2.y, accB);
                accC = fma2(qb[2*d4],   k2.x, accC);
                accD = fma2(qb[2*d4+1], k2.y, accD);
            }
            float2 fa = unpack2(accA), fb = unpack2(accB);
            float2 fc = unpack2(accC), fd = unpack2(accD);
            float sA = ((fa.x + fa.y) + (fb.x + fb.y)) * scale + dA[kk];
            float sB = ((fc.x + fc.y) + (fd.x + fd.y)) * scale + dB[kk];
            sva[kk] = sA; svb[kk] = sB;
            smaxa = fmaxf(smaxa, sA);
            smaxb = fmaxf(smaxb, sB);
        }
        float mna = fmaxf(ma, smaxa);
        if (__any_sync(0xFFFFFFFFu, mna > ma)) {
            float corr = __expf(ma - mna);
            la *= corr;
            unsigned long long cc = pack2(corr, corr);
            #pragma unroll
            for (int d = 0; d < 16; d++) oa[d] = mul2(oa[d], cc);
            ma = mna;
        }
        float mnb = fmaxf(mb, smaxb);
        if (__any_sync(0xFFFFFFFFu, mnb > mb)) {
            float corr = __expf(mb - mnb);
            lb *= corr;
            unsigned long long cc = pack2(corr, corr);
            #pragma unroll
            for (int d = 0; d < 16; d++) ob[d] = mul2(ob[d], cc);
            mb = mnb;
        }
        #pragma unroll
        for (int kk = 0; kk < 8; kk++) {
            float pA = __expf(sva[kk] - ma);
            float pB = __expf(svb[kk] - mb);
            la += pA; lb += pB;
            unsigned long long p2a = pack2(pA, pA);
            unsigned long long p2b = pack2(pB, pB);
            const ulonglong2* vp = (const ulonglong2*)(Vc + kk * 256 + (h << 5));
            #pragma unroll
            for (int d4 = 0; d4 < 8; d4++) {
                ulonglong2 v2 = vp[d4];
                oa[2*d4]   = fma2(v2.x, p2a, oa[2*d4]);
                oa[2*d4+1] = fma2(v2.y, p2a, oa[2*d4+1]);
                ob[2*d4]   = fma2(v2.x, p2b, ob[2*d4]);
                ob[2*d4+1] = fma2(v2.y, p2b, ob[2*d4+1]);
            }
        }

        if (kt < 127) {
            const int nxt = cur ^ 1;
            ((float4*)Ks[nxt])[t]       = pk0;
            ((float4*)Ks[nxt])[t + 256] = pk1;
            ((float4*)Vs[nxt])[t]       = pv0;
            ((float4*)Vs[nxt])[t + 256] = pv1;
            *(float2*)(&ds[nxt][drow * 10 + dcol]) = pd;
        }
        __syncthreads();
    }

    float inva = 1.f / la, invb = 1.f / lb;
    float* op0 = g_AO + ((long)(b * NN + qbase + q)) * HIDD + (h << 5);
    float* op1 = g_AO + ((long)(b * NN + qbase + q + 32)) * HIDD + (h << 5);
    #pragma unroll
    for (int d4 = 0; d4 < 8; d4++) {
        float2 a0 = unpack2(oa[2*d4]), a1 = unpack2(oa[2*d4+1]);
        float2 b0 = unpack2(ob[2*d4]), b1 = unpack2(ob[2*d4+1]);
        ((float4*)op0)[d4] = make_float4(a0.x * inva, a0.y * inva, a1.x * inva, a1.y * inva);
        ((float4*)op1)[d4] = make_float4(b0.x * invb, b0.y * invb, b1.x * invb, b1.y * invb);
    }
}

// ============================================================
// Node scores: s = tanh((x . w) / ||w||). One warp per node.
// ============================================================
__global__ __launch_bounds__(256) void score_kernel(const float* __restrict__ w)
{
    int warp = (blockIdx.x * blockDim.x + threadIdx.x) >> 5;
    int lane = threadIdx.x & 31;
    if (warp >= BB * NN) return;
    const float* x = g_ENC + (long)warp * HIDD;
    float sx = 0.f, sw = 0.f;
    #pragma unroll
    for (int i = lane; i < HIDD; i += 32) {
        float wv = w[i];
        sx += x[i] * wv;
        sw += wv * wv;
    }
    #pragma unroll
    for (int off = 16; off; off >>= 1) {
        sx += __shfl_xor_sync(0xFFFFFFFFu, sx, off);
        sw += __shfl_xor_sync(0xFFFFFFFFu, sw, off);
    }
    if (lane == 0) g_score[warp] = tanhf(sx / sqrtf(sw));
}

// ============================================================
// Top-K per graph: bitonic sort of 1024 (desc score, asc index).
// ============================================================
__global__ __launch_bounds__(1024) void topk_kernel(float* __restrict__ out_perm)
{
    __shared__ unsigned long long s[NN];
    const int b = blockIdx.x, t = threadIdx.x;
    float sc = g_score[b * NN + t];
    unsigned u = __float_as_uint(sc);
    u = (u & 0x80000000u) ? ~u : (u | 0x80000000u);
    u = ~u;                                            // descending
    s[t] = (((unsigned long long)u) << 32) | (unsigned)t;
    g_nodemap[b * NN + t] = -1;
    __syncthreads();
    for (unsigned k = 2; k <= NN; k <<= 1)
        for (unsigned j = k >> 1; j; j >>= 1) {
            unsigned i = t, ixj = i ^ j;
            if (ixj > i) {
                bool up = ((i & k) == 0);
                unsigned long long a = s[i], c = s[ixj];
                if ((a > c) == up) { s[i] = c; s[ixj] = a; }
            }
            __syncthreads();
        }
    if (t < KKP) {
        int node = (int)(s[t] & 0xFFFFFFFFu);
        g_perm[b * KKP + t] = node;
        g_vals[b * KKP + t] = g_score[b * NN + node];
        out_perm[b * KKP + t] = (float)node;
        g_nodemap[b * NN + node] = t;
    }
}

// ============================================================
// sub_x gather
// ============================================================
__global__ __launch_bounds__(256) void subx_kernel(float* __restrict__ out)
{
    const int row = blockIdx.x;
    const int b = row / KKP;
    const int node = g_perm[row];
    const float val = g_vals[row];
    const float* src = g_ENC + ((long)b * NN + node) * HIDD;
    out[(long)row * HIDD + threadIdx.x] = src[threadIdx.x] * val;
}

// ============================================================
// Edge pipeline (multi-kernel bitonic).
// ============================================================
__global__ __launch_bounds__(256) void edge_build(const void* __restrict__ eiraw)
{
    __shared__ int s_is64;
    if (threadIdx.x == 0) {
        const unsigned* w32 = (const unsigned*)eiraw;
        int all0 = 1;
        for (int i = 0; i < 64; i++)
            if (w32[2 * i + 1] != 0u) { all0 = 0; break; }
        s_is64 = all0;
    }
    __syncthreads();
    const int is64 = s_is64;
    const int total = BB * EPER;
    for (int idx = blockIdx.x * blockDim.x + threadIdx.x; idx < total;
         idx += gridDim.x * blockDim.x) {
        int b = idx >> 14;
        long long vs, vd;
        if (is64) {
            const long long* ei = (const long long*)eiraw;
            vs = ei[idx];
            vd = ei[total + idx];
        } else {
            const int* ei = (const int*)eiraw;
            vs = ei[idx];
            vd = ei[total + idx];
        }
        int src = (int)(vs - (long long)b * NN);
        int dst = (int)(vd - (long long)b * NN);
        src = min(max(src, 0), NN - 1);
        dst = min(max(dst, 0), NN - 1);
        int nu = g_nodemap[b * NN + src];
        int nv = g_nodemap[b * NN + dst];
        bool valid = (nu >= 0) && (nv >= 0);
        unsigned key = valid ? (unsigned)(nu * KKP + nv) : (unsigned)(KKP * KKP);
        int ou = valid ? nu : -1, ov = valid ? nv : -1;
        g_es[idx] = (((unsigned long long)key) << 21)
                  | (((unsigned long long)(ou + 1)) << 11)
                  | (((unsigned long long)(ov + 1)) << 1)
                  | (valid ? 1ull : 0ull);
    }
}

__global__ __launch_bounds__(1024) void edge_sort_seg()
{
    __shared__ unsigned long long sh[4096];
    const int b = blockIdx.x >> 2, seg = blockIdx.x & 3;
    const int t = threadIdx.x;
    unsigned long long* es = g_es + (long)b * EPER + seg * 4096;
    for (int i = t; i < 4096; i += 1024) sh[i] = es[i];
    __syncthreads();
    for (unsigned k = 2; k <= 4096; k <<= 1)
        for (unsigned j = k >> 1; j; j >>= 1) {
            for (int loc = t; loc < 4096; loc += 1024) {
                unsigned i2 = (unsigned)loc, ixj = i2 ^ j;
                if (ixj > i2) {
                    unsigned gi = seg * 4096 + i2;
                    bool up = ((gi & k) == 0);
                    unsigned long long a = sh[i2], c = sh[ixj];
                    if ((a > c) == up) { sh[i2] = c; sh[ixj] = a; }
                }
            }
            __syncthreads();
        }
    for (int i = t; i < 4096; i += 1024) es[i] = sh[i];
}

__global__ __launch_bounds__(1024) void edge_gmerge(unsigned k, unsigned j)
{
    int loc = blockIdx.x * blockDim.x + threadIdx.x;
    unsigned i = (unsigned)(loc & (EPER - 1));
    int b = loc >> 14;
    unsigned ixj = i ^ j;
    if (ixj > i) {
        unsigned long long* es = g_es + (long)b * EPER;
        bool up = ((i & k) == 0);
        unsigned long long a = es[i], c = es[ixj];
        if ((a > c) == up) { es[i] = c; es[ixj] = a; }
    }
}

__global__ __launch_bounds__(1024) void edge_smerge(unsigned k)
{
    __shared__ unsigned long long sh[4096];
    const int b = blockIdx.x >> 2, seg = blockIdx.x & 3;
    const int t = threadIdx.x;
    unsigned long long* es = g_es + (long)b * EPER + seg * 4096;
    for (int i = t; i < 4096; i += 1024) sh[i] = es[i];
    __syncthreads();
    for (unsigned j = 2048; j; j >>= 1) {
        for (int loc = t; loc < 4096; loc += 1024) {
            unsigned i2 = (unsigned)loc, ixj = i2 ^ j;
            if (ixj > i2) {
                unsigned gi = seg * 4096 + i2;
                bool up = ((gi & k) == 0);
                unsigned long long a = sh[i2], c = sh[ixj];
                if ((a > c) == up) { sh[i2] = c; sh[ixj] = a; }
            }
        }
        __syncthreads();
    }
    for (int i = t; i < 4096; i += 1024) es[i] = sh[i];
}

__global__ __launch_bounds__(256) void edge_emit(
    float* __restrict__ out_e, float* __restrict__ out_valid)
{
    const int total = BB * EPER;
    for (int idx = blockIdx.x * blockDim.x + threadIdx.x; idx < total;
         idx += gridDim.x * blockDim.x) {
        int b = idx >> 14, e = idx & (EPER - 1);
        unsigned long long p = g_es[idx];
        int ou = (int)((p >> 11) & 0x3FFu) - 1;
        int ov = (int)((p >> 1) & 0x3FFu) - 1;
        out_e[(long)b * 2 * EPER + e]        = (float)ou;
        out_e[(long)b * 2 * EPER + EPER + e] = (float)ov;
        out_valid[(long)b * EPER + e]        = (float)(p & 1ull);
    }
}

// ============================================================
extern "C" void kernel_launch(void* const* d_in, const int* in_sizes, int n_in,
                              void* d_out, int out_size)
{
    const float* X    = (const float*)d_in[0];
    const void*  EI   = d_in[1];
    const float* DIST = (const float*)d_in[3];
    const float* Wq   = (const float*)d_in[5];
    const float* Wk   = (const float*)d_in[6];
    const float* Wv   = (const float*)d_in[7];
    const float* Wo   = (const float*)d_in[8];
    const float* tw   = (const float*)d_in[9];
    float* out = (float*)d_out;

    gemm_k<<<dim3(4, 64), 256>>>(X, Wq, 0, out + OFF_ENC);
    gemm_k<<<dim3(4, 64), 256>>>(X, Wk, 1, out + OFF_ENC);
    gemm_k<<<dim3(4, 64), 256>>>(X, Wv, 2, out + OFF_ENC);

    attn_kernel<<<dim3(16, 8), 256>>>(DIST);

    gemm_k<<<dim3(4, 64), 256>>>(X, Wo, 3, out + OFF_ENC);

    score_kernel<<<(BB * NN * 32) / 256, 256>>>(tw);
    topk_kernel<<<BB, NN>>>(out + OFF_PERM);
    subx_kernel<<<BB * KKP, 256>>>(out + OFF_SUBX);

    edge_build<<<128, 256>>>(EI);
    edge_sort_seg<<<32, 1024>>>();
    edge_gmerge<<<128, 1024>>>(8192u, 4096u);
    edge_smerge<<<32, 1024>>>(8192u);
    edge_gmerge<<<128, 1024>>>(16384u, 8192u);
    edge_gmerge<<<128, 1024>>>(16384u, 4096u);
    edge_smerge<<<32, 1024>>>(16384u);
    edge_emit<<<128, 256>>>(out + OFF_EDGE, out + OFF_VALID);
}